// round 13
// baseline (speedup 1.0000x reference)
#include <cuda_runtime.h>
#include <math.h>
#include <stdint.h>

#define T_STEPS 16
#define BATCH   64
#define DG      512
#define DH      1024
#define DOUT    512
#define S_STEPS 3
#define LAMBDA  0.95f
#define ETA     0.5f

#define NBLK 64
#define NTHR 512
#define KTOT 1536            // combined K: 1024 (W_h) + 512 (W_g)
#define KF8  (KTOT / 8)      // 192
#define KF8_HEAD (DH / 8)    // 128

// ---------------- device scratch ----------------
__device__ float g_h[BATCH * DH];
__device__ float g_hbase[BATCH * DH];          // full GEMM result (+bias), no partials
__device__ float g_hist[T_STEPS - 1][BATCH * DH];
__device__ float g_gram[BATCH * 256];
__device__ float g_hsum[BATCH * 16];
__device__ float g_pred[BATCH * DOUT];
__device__ float g_lossb[BATCH];
__device__ float g_accb[BATCH];

// pre-packed tf32 hi/lo fragments: combined [W_h | W_g] and head_W
__device__ float g_wf_hi[DH * KTOT];
__device__ float g_wf_lo[DH * KTOT];
__device__ float g_hwf_hi[DOUT * DH];
__device__ float g_hwf_lo[DOUT * DH];

// grid barrier
__device__ unsigned g_bar_cnt = 0;
__device__ volatile unsigned g_bar_gen = 0;

__device__ __forceinline__ void bar_sync(unsigned& gen) {
    __syncthreads();
    if (threadIdx.x == 0) {
        __threadfence();
        unsigned t = atomicAdd(&g_bar_cnt, 1u);
        if (t == NBLK - 1) {
            g_bar_cnt = 0u;
            __threadfence();
            g_bar_gen = gen + 1u;
        } else {
            while (g_bar_gen == gen) __nanosleep(32);
        }
    }
    __syncthreads();
    gen++;
}

// ---------------- tf32 helpers ----------------
__device__ __forceinline__ uint32_t f2tf32(float x) {
    uint32_t r;
    asm("cvt.rna.tf32.f32 %0, %1;" : "=r"(r) : "f"(x));
    return r;
}

__device__ __forceinline__ void mma8(float* c, uint4 a, uint32_t b0, uint32_t b1) {
    asm volatile(
        "mma.sync.aligned.m16n8k8.row.col.f32.tf32.tf32.f32 "
        "{%0,%1,%2,%3}, {%4,%5,%6,%7}, {%8,%9}, {%0,%1,%2,%3};"
        : "+f"(c[0]), "+f"(c[1]), "+f"(c[2]), "+f"(c[3])
        : "r"(a.x), "r"(a.y), "r"(a.z), "r"(a.w), "r"(b0), "r"(b1));
}

// ---------------- B-fragment prepack ----------------
// W row-major [N][Ksrc] -> frag buffer with kfrag8 k8-columns, dst k8 offset.
__device__ void pack_w(const float* __restrict__ W, float* __restrict__ hi,
                       float* __restrict__ lo, int NK, int klog, int kfrag8,
                       int k8off) {
    const int kmask = (1 << klog) - 1;
    for (int idx = blockIdx.x * NTHR + threadIdx.x; idx < NK; idx += NBLK * NTHR) {
        int n = idx >> klog, k = idx & kmask;
        float v = W[idx];
        uint32_t hb = f2tf32(v);
        uint32_t lb = f2tf32(v - __uint_as_float(hb));
        int n8 = n >> 3, k8 = (k >> 3) + k8off;
        int lane = (n & 7) * 4 + (k & 3);
        int reg = (k >> 2) & 1;
        size_t a = ((size_t)(n8 * kfrag8 + k8) * 32 + lane) * 2 + reg;
        hi[a] = __uint_as_float(hb);
        lo[a] = __uint_as_float(lb);
    }
}

// ---------------- step GEMM: hbase = [h|z_t] @ [W_h|W_g]^T + b_h --------
// Block bi owns n-slice [bi*16, bi*16+16), full K=1536.
// 16 warps: mw(4) x nt(2) x kd(2). kd splits each 64-k chunk's 8 k8 in half.
__device__ void step_gemm(int bi, int t, const float* __restrict__ z_seq,
                          const float* __restrict__ b_h,
                          uint32_t* As_hi, uint32_t* As_lo, float* smC) {
    const int tid = threadIdx.x, warp = tid >> 5, lane = tid & 31;
    const int mw = warp >> 2, nt = (warp >> 1) & 1, kd = warp & 1;
    const int gid = lane >> 2, tig = lane & 3;
    const int row = tid >> 3, cseg = tid & 7;
    const int n8g = bi * 2 + nt;

    float c[4] = {0.f, 0.f, 0.f, 0.f};

#pragma unroll 1
    for (int ch = 0; ch < 24; ch++) {
        __syncthreads();
        {   // cooperative A-pack of one 64x64 chunk (hi/lo)
            const float4* p;
            if (ch < 16)
                p = (const float4*)(g_h + (size_t)row * DH + ch * 64 + cseg * 8);
            else
                p = (const float4*)(z_seq + ((size_t)t * BATCH + row) * DG +
                                    (ch - 16) * 64 + cseg * 8);
            float4 v0 = __ldcg(p), v1 = __ldcg(p + 1);
            float xv[8] = {v0.x, v0.y, v0.z, v0.w, v1.x, v1.y, v1.z, v1.w};
            const int tr = row & 15, mt = row >> 4;
#pragma unroll
            for (int cc = 0; cc < 8; cc++) {
                int reg = (tr >= 8 ? 1 : 0) + (cc >= 4 ? 2 : 0);
                int ln = (tr & 7) * 4 + (cc & 3);
                int ix = ((cseg * 4 + mt) * 32 + ln) * 4 + reg;
                uint32_t hb = f2tf32(xv[cc]);
                As_hi[ix] = hb;
                As_lo[ix] = f2tf32(xv[cc] - __uint_as_float(hb));
            }
        }
        __syncthreads();
        const int k8b = ch * 8;
#pragma unroll
        for (int j = 0; j < 4; j++) {
            const int k8 = kd * 4 + j;
            const int ai = ((k8 * 4 + mw) * 32 + lane) * 4;
            uint4 ah = *(const uint4*)&As_hi[ai];
            uint4 al = *(const uint4*)&As_lo[ai];
            const size_t ba = ((size_t)(n8g * KF8 + k8b + k8) * 32 + lane) * 2;
            float2 bh = *(const float2*)&g_wf_hi[ba];
            float2 bl = *(const float2*)&g_wf_lo[ba];
            uint32_t bh0 = __float_as_uint(bh.x), bh1 = __float_as_uint(bh.y);
            mma8(c, ah, bh0, bh1);
            mma8(c, ah, __float_as_uint(bl.x), __float_as_uint(bl.y));
            mma8(c, al, bh0, bh1);
        }
    }

    // k-reduce across kd via smem, add bias, store full-K result
    __syncthreads();
    {
        const int r0 = mw * 16 + gid, cb = nt * 8 + tig * 2;
        smC[kd * 1024 + r0 * 16 + cb]           = c[0];
        smC[kd * 1024 + r0 * 16 + cb + 1]       = c[1];
        smC[kd * 1024 + (r0 + 8) * 16 + cb]     = c[2];
        smC[kd * 1024 + (r0 + 8) * 16 + cb + 1] = c[3];
    }
    __syncthreads();
    for (int idx = tid; idx < 1024; idx += NTHR) {
        const int n = idx & 15;
        float v = smC[idx] + smC[1024 + idx] + b_h[bi * 16 + n];
        g_hbase[(size_t)(idx >> 4) * DH + bi * 16 + n] = v;
    }
}

// ---------------- head GEMM: pred = h @ head_W^T + head_b ---------------
// Block bi owns n-slice [bi*8, bi*8+8), full K=1024. warps: mw(4) x kd(4).
__device__ void head_gemm(int bi, const float* __restrict__ head_b,
                          uint32_t* As_hi, uint32_t* As_lo, float* smC) {
    const int tid = threadIdx.x, warp = tid >> 5, lane = tid & 31;
    const int mw = warp >> 2, kd = warp & 3;
    const int gid = lane >> 2, tig = lane & 3;
    const int row = tid >> 3, cseg = tid & 7;

    float c[4] = {0.f, 0.f, 0.f, 0.f};

#pragma unroll 1
    for (int ch = 0; ch < 16; ch++) {
        __syncthreads();
        {
            const float4* p = (const float4*)(g_h + (size_t)row * DH +
                                              ch * 64 + cseg * 8);
            float4 v0 = __ldcg(p), v1 = __ldcg(p + 1);
            float xv[8] = {v0.x, v0.y, v0.z, v0.w, v1.x, v1.y, v1.z, v1.w};
            const int tr = row & 15, mt = row >> 4;
#pragma unroll
            for (int cc = 0; cc < 8; cc++) {
                int reg = (tr >= 8 ? 1 : 0) + (cc >= 4 ? 2 : 0);
                int ln = (tr & 7) * 4 + (cc & 3);
                int ix = ((cseg * 4 + mt) * 32 + ln) * 4 + reg;
                uint32_t hb = f2tf32(xv[cc]);
                As_hi[ix] = hb;
                As_lo[ix] = f2tf32(xv[cc] - __uint_as_float(hb));
            }
        }
        __syncthreads();
        const int k8b = ch * 8;
#pragma unroll
        for (int j = 0; j < 2; j++) {
            const int k8 = kd * 2 + j;
            const int ai = ((k8 * 4 + mw) * 32 + lane) * 4;
            uint4 ah = *(const uint4*)&As_hi[ai];
            uint4 al = *(const uint4*)&As_lo[ai];
            const size_t ba = ((size_t)(bi * KF8_HEAD + k8b + k8) * 32 + lane) * 2;
            float2 bh = *(const float2*)&g_hwf_hi[ba];
            float2 bl = *(const float2*)&g_hwf_lo[ba];
            uint32_t bh0 = __float_as_uint(bh.x), bh1 = __float_as_uint(bh.y);
            mma8(c, ah, bh0, bh1);
            mma8(c, ah, __float_as_uint(bl.x), __float_as_uint(bl.y));
            mma8(c, al, bh0, bh1);
        }
    }

    __syncthreads();
    {
        const int r0 = mw * 16 + gid, cb = tig * 2;
        smC[kd * 512 + r0 * 8 + cb]           = c[0];
        smC[kd * 512 + r0 * 8 + cb + 1]       = c[1];
        smC[kd * 512 + (r0 + 8) * 8 + cb]     = c[2];
        smC[kd * 512 + (r0 + 8) * 8 + cb + 1] = c[3];
    }
    __syncthreads();
    {
        const int n = tid & 7;
        float v = smC[tid] + smC[512 + tid] + smC[1024 + tid] + smC[1536 + tid] +
                  head_b[bi * 8 + n];
        g_pred[(size_t)(tid >> 3) * DOUT + bi * 8 + n] = v;
    }
}

// ---------------- 512-thread multi-value block reduction ----------------
template <int NV>
__device__ __forceinline__ void reduce512(const float* v, float* bc, float (*red)[18]) {
    const int lane = threadIdx.x & 31, warp = threadIdx.x >> 5;
#pragma unroll
    for (int x = 0; x < NV; x++) {
        float s = v[x];
#pragma unroll
        for (int o = 16; o > 0; o >>= 1) s += __shfl_down_sync(0xffffffffu, s, o);
        if (lane == 0) red[warp][x] = s;
    }
    __syncthreads();
#pragma unroll
    for (int x = warp; x < NV; x += 16) {
        float s = (lane < 16) ? red[lane][x] : 0.f;
#pragma unroll
        for (int o = 8; o > 0; o >>= 1) s += __shfl_down_sync(0xffffffffu, s, o);
        if (lane == 0) bc[x] = s;
    }
    __syncthreads();
}

// ---------------- refine phase (block = batch element) ------------------
__device__ void refine_phase(int b, int t, bool last,
                             const float* __restrict__ gam,
                             const float* __restrict__ bet,
                             const float* __restrict__ alp) {
    const int tid = threadIdx.x, lane = tid & 31, warp = tid >> 5;
    const int i0 = tid, i1 = tid + 512;

    __shared__ float red[16][18];
    __shared__ float bcS[18];
    __shared__ float bc0[18];
    __shared__ float Gs[256];
    __shared__ float hsums[16];
    __shared__ float es[16];
    __shared__ float coef[4];

    const float g0 = gam[i0], g1 = gam[i1];
    const float be0 = bet[i0], be1 = bet[i1];

    // hbase row: full GEMM result incl. z-part and bias (4 KB, cross-block)
    float hb0 = __ldcg(&g_hbase[(size_t)b * DH + i0]);
    float hb1 = __ldcg(&g_hbase[(size_t)b * DH + i1]);

    float hv0[15], hv1[15];
#pragma unroll
    for (int tau = 0; tau < 15; tau++) {
        hv0[tau] = g_hist[tau][b * DH + i0];   // same-block, L1-resident
        hv1[tau] = g_hist[tau][b * DH + i1];
    }

    if (tid < 256) Gs[tid] = g_gram[b * 256 + tid];
    if (tid < 16)  hsums[tid] = g_hsum[b * 16 + tid];

    {
        float p[17];
#pragma unroll
        for (int tau = 0; tau < 15; tau++)
            p[tau] = hv0[tau] * hb0 + hv1[tau] * hb1;
        p[15] = hb0 + hb1;
        p[16] = hb0 * hb0 + hb1 * hb1;
        reduce512<17>(p, bc0, red);
    }

    float mu = bc0[15] * (1.f / DH);
    float var = bc0[16] * (1.f / DH) - mu * mu;
    float rstd = rsqrtf(var + 1e-5f);
    float h0 = fmaxf((hb0 - mu) * rstd * g0 + be0, 0.f);
    float h1 = fmaxf((hb1 - mu) * rstd * g1 + be1, 0.f);

    const float alpha = *alp;
    float wdl = 0.f;
    if (warp == 0 && lane < t)
        wdl = ETA * powf(LAMBDA, (float)(t - 1 - lane));

#pragma unroll
    for (int s = 0; s < S_STEPS; s++) {
        {
            float qv[16];
#pragma unroll
            for (int tau = 0; tau < 15; tau++)
                qv[tau] = hv0[tau] * h0 + hv1[tau] * h1;
            qv[15] = h0 * h0 + h1 * h1;
            reduce512<16>(qv, bcS, red);
        }

        if (warp == 0) {
            float d = (lane < 16) ? bcS[lane] : 0.f;
            float e = wdl * d;
            if (lane < 16) es[lane] = e;
            __syncwarp();
            float f = 0.f;
            if (lane < 16) {
#pragma unroll
                for (int sg = 0; sg < 15; sg++)
                    f += es[sg] * Gs[lane * 16 + sg];
            }
            float hbd = (lane < 16) ? bc0[lane] : 0.f;
            float hsm = (lane < 16) ? hsums[lane] : 0.f;
            float pA = e * d;
            float pB = e * hbd;
            float pC = e * hsm;
            float pD = e * f;
#pragma unroll
            for (int o = 8; o > 0; o >>= 1) {
                pA += __shfl_down_sync(0xffffffffu, pA, o);
                pB += __shfl_down_sync(0xffffffffu, pB, o);
                pC += __shfl_down_sync(0xffffffffu, pC, o);
                pD += __shfl_down_sync(0xffffffffu, pD, o);
            }
            if (lane == 0) {
                float c1, c2;
                if (!last) {
                    float hh = bcS[15];
                    float n1 = sqrtf(hh) + 1e-6f;
                    float n2 = sqrtf(fmaxf(pD, 0.f)) + 1e-6f;
                    float R  = pA / (n1 * n2 + 1e-6f);
                    float Rp = fminf(fmaxf(R, 0.f), 1.f);
                    float spp = fmaxf(alpha, 0.f) + log1pf(expf(-fabsf(alpha)));
                    float spn = fmaxf(-alpha, 0.f) + log1pf(expf(-fabsf(alpha)));
                    float kco = (alpha >= 0.f) ? (1.f + spp) : (1.f / (1.f + spn));
                    float a   = 1.f - powf(1.f - Rp, kco);
                    c1 = 1.f - a * a;
                    c2 = a;
                } else {
                    c1 = 1.f;
                    c2 = 1.f;
                }
                float sum_hn  = c1 * bc0[15] + c2 * pC;
                float sum_hn2 = c1 * c1 * bc0[16] + 2.f * c1 * c2 * pB +
                                c2 * c2 * pD;
                float mu_n  = sum_hn * (1.f / DH);
                float var_n = sum_hn2 * (1.f / DH) - mu_n * mu_n;
                coef[0] = c1;
                coef[1] = c2;
                coef[2] = mu_n;
                coef[3] = rsqrtf(var_n + 1e-5f);
            }
        }
        __syncthreads();

        float Ah0 = 0.f, Ah1 = 0.f;
#pragma unroll
        for (int tau = 0; tau < 15; tau++) {
            Ah0 += es[tau] * hv0[tau];
            Ah1 += es[tau] * hv1[tau];
        }
        const float c1 = coef[0], c2 = coef[1], mun = coef[2], rsn = coef[3];
        float hn0 = c1 * hb0 + c2 * Ah0;
        float hn1 = c1 * hb1 + c2 * Ah1;
        h0 = fmaxf((hn0 - mun) * rsn * g0 + be0, 0.f);
        h1 = fmaxf((hn1 - mun) * rsn * g1 + be1, 0.f);
        __syncthreads();
    }

    g_h[b * DH + i0] = h0;
    g_h[b * DH + i1] = h1;

    if (!last) {
        float r[17];
#pragma unroll
        for (int tau = 0; tau < 15; tau++)
            r[tau] = hv0[tau] * h0 + hv1[tau] * h1;
        r[15] = h0 + h1;
        r[16] = h0 * h0 + h1 * h1;
        reduce512<17>(r, bcS, red);
        if (tid < t) {
            g_gram[b * 256 + t * 16 + tid] = bcS[tid];
            g_gram[b * 256 + tid * 16 + t] = bcS[tid];
        }
        if (tid == 0) {
            g_gram[b * 256 + t * 16 + t] = bcS[16];
            g_hsum[b * 16 + t] = bcS[15];
        }
        g_hist[t][b * DH + i0] = h0;
        g_hist[t][b * DH + i1] = h1;
    }
}

// ---------------- loss phase ----------------
__device__ void loss_phase(int b, const float* __restrict__ clean) {
    const int o = threadIdx.x;
    __shared__ float red[16][18];
    __shared__ float bc[18];
    float pred = __ldcg(&g_pred[(size_t)b * DOUT + o]);
    float c = clean[b * DOUT + o];
    float d = pred - c;
    float v[4] = {pred * c, pred * pred, c * c, d * d};
    reduce512<4>(v, bc, red);
    if (o == 0) {
        g_lossb[b] = bc[3] / (bc[2] + 1e-6f);
        g_accb[b]  = bc[0] / ((sqrtf(bc[1]) + 1e-6f) * (sqrtf(bc[2]) + 1e-6f));
    }
}

// ---------------- the one persistent kernel ----------------
__global__ void __launch_bounds__(NTHR, 1) fused_kernel(
    const float* __restrict__ z_seq, const float* __restrict__ clean,
    const float* __restrict__ W_h, const float* __restrict__ W_g,
    const float* __restrict__ b_h, const float* __restrict__ ln_g,
    const float* __restrict__ ln_b, const float* __restrict__ alpha,
    const float* __restrict__ head_W, const float* __restrict__ head_b,
    float* __restrict__ out) {
    __shared__ __align__(16) uint32_t As_hi[4096];   // 16 KB
    __shared__ __align__(16) uint32_t As_lo[4096];   // 16 KB
    __shared__ float smC[2048];                      // 8 KB k-reduce buffer

    unsigned gen = g_bar_gen;
    const int bi = blockIdx.x;

    // phase 0: zero h, prepack weights (combined [W_h|W_g] and head_W)
    g_h[bi * 1024 + threadIdx.x] = 0.f;
    g_h[bi * 1024 + threadIdx.x + 512] = 0.f;
    pack_w(W_h,    g_wf_hi,  g_wf_lo,  DH * DH,   10, KF8, 0);
    pack_w(W_g,    g_wf_hi,  g_wf_lo,  DH * DG,    9, KF8, 128);
    pack_w(head_W, g_hwf_hi, g_hwf_lo, DOUT * DH, 10, KF8_HEAD, 0);
    bar_sync(gen);

    for (int t = 0; t < T_STEPS; t++) {
        step_gemm(bi, t, z_seq, b_h, As_hi, As_lo, smC);
        bar_sync(gen);
        refine_phase(bi, t, t == T_STEPS - 1, ln_g, ln_b, alpha);
        bar_sync(gen);
    }

    head_gemm(bi, head_b, As_hi, As_lo, smC);
    bar_sync(gen);

    loss_phase(bi, clean);
    bar_sync(gen);

    if (bi == 0 && threadIdx.x < 32) {
        const int lane = threadIdx.x;
        float l = g_lossb[lane] + g_lossb[lane + 32];
        float a = g_accb[lane] + g_accb[lane + 32];
#pragma unroll
        for (int o = 16; o > 0; o >>= 1) {
            l += __shfl_down_sync(0xffffffffu, l, o);
            a += __shfl_down_sync(0xffffffffu, a, o);
        }
        if (lane == 0) {
            out[0] = l * (1.f / BATCH);
            out[1] = a * (1.f / BATCH);
        }
    }
}

// ---------------- launch ----------------
extern "C" void kernel_launch(void* const* d_in, const int* in_sizes, int n_in,
                              void* d_out, int out_size) {
    const float* z_seq  = (const float*)d_in[0];
    const float* clean  = (const float*)d_in[1];
    const float* W_h    = (const float*)d_in[2];
    const float* W_g    = (const float*)d_in[3];
    const float* b_h    = (const float*)d_in[4];
    const float* ln_g   = (const float*)d_in[5];
    const float* ln_b   = (const float*)d_in[6];
    const float* alpha  = (const float*)d_in[7];
    const float* head_W = (const float*)d_in[8];
    const float* head_b = (const float*)d_in[9];
    float* out = (float*)d_out;

    fused_kernel<<<NBLK, NTHR>>>(z_seq, clean, W_h, W_g, b_h, ln_g, ln_b,
                                 alpha, head_W, head_b, out);
}

// round 14
// speedup vs baseline: 2.9192x; 2.9192x over previous
#include <cuda_runtime.h>
#include <math.h>
#include <stdint.h>

#define T_STEPS 16
#define BATCH   64
#define DG      512
#define DH      1024
#define DOUT    512
#define S_STEPS 3
#define LAMBDA  0.95f
#define ETA     0.5f

#define NBLK 128
#define NTHR 1024
#define KS_H 8
#define KS_O 8

// ---------------- device scratch ----------------
__device__ float g_h[BATCH * DH];
__device__ float g_parts[KS_H][BATCH * DH];
__device__ float g_zwg[T_STEPS * BATCH * DH];
__device__ float g_hist[T_STEPS - 1][BATCH * DH];
__device__ float g_gram[BATCH * 256];
__device__ float g_hsum[BATCH * 16];
__device__ float g_hp[KS_O][BATCH * DOUT];
__device__ float g_lossb[BATCH];
__device__ float g_accb[BATCH];

// pre-packed tf32 hi/lo B-fragments
__device__ float g_whf_hi[DH * DH];
__device__ float g_whf_lo[DH * DH];
__device__ float g_wgf_hi[DH * DG];
__device__ float g_wgf_lo[DH * DG];
__device__ float g_hwf_hi[DOUT * DH];
__device__ float g_hwf_lo[DOUT * DH];

// grid barrier (pure spin, no nanosleep)
__device__ unsigned g_bar_cnt = 0;
__device__ volatile unsigned g_bar_gen = 0;

__device__ __forceinline__ void bar_sync(unsigned& gen) {
    __syncthreads();
    if (threadIdx.x == 0) {
        __threadfence();
        unsigned t = atomicAdd(&g_bar_cnt, 1u);
        if (t == NBLK - 1) {
            g_bar_cnt = 0u;
            __threadfence();
            g_bar_gen = gen + 1u;
        } else {
            while (g_bar_gen == gen) { }
        }
    }
    __syncthreads();
    gen++;
}

// ---------------- tf32 helpers ----------------
__device__ __forceinline__ uint32_t f2tf32(float x) {
    uint32_t r;
    asm("cvt.rna.tf32.f32 %0, %1;" : "=r"(r) : "f"(x));
    return r;
}

__device__ __forceinline__ void mma8(float* c, uint4 a, uint32_t b0, uint32_t b1) {
    asm volatile(
        "mma.sync.aligned.m16n8k8.row.col.f32.tf32.tf32.f32 "
        "{%0,%1,%2,%3}, {%4,%5,%6,%7}, {%8,%9}, {%0,%1,%2,%3};"
        : "+f"(c[0]), "+f"(c[1]), "+f"(c[2]), "+f"(c[3])
        : "r"(a.x), "r"(a.y), "r"(a.z), "r"(a.w), "r"(b0), "r"(b1));
}

// ---------------- B-fragment prepack ----------------
__device__ void pack_w(const float* __restrict__ W, float* __restrict__ hi,
                       float* __restrict__ lo, int NK, int klog, int kfrag8) {
    const int kmask = (1 << klog) - 1;
    for (int idx = blockIdx.x * NTHR + threadIdx.x; idx < NK; idx += NBLK * NTHR) {
        int n = idx >> klog, k = idx & kmask;
        float v = W[idx];
        uint32_t hb = f2tf32(v);
        uint32_t lb = f2tf32(v - __uint_as_float(hb));
        int n8 = n >> 3, k8 = k >> 3;
        int lane = (n & 7) * 4 + (k & 3);
        int reg = (k >> 2) & 1;
        size_t a = ((size_t)(n8 * kfrag8 + k8) * 32 + lane) * 2 + reg;
        hi[a] = __uint_as_float(hb);
        lo[a] = __uint_as_float(lb);
    }
}

// ---------------- tf32x3 GEMM: 64m x 64n block tile, 1024 threads -------
// 32 warps: mw(4) x nt(2) x kd(4). kd k-splits each 64-k chunk (2 k8 each).
// out[m][n8base*8 + n] = sum over k in [xk0, xk0 + nch*64) of X[m][k]*W[n][k]
__device__ void gemm64(const float* __restrict__ X, int ldx, int xk0,
                       const float* __restrict__ Bhi, const float* __restrict__ Blo,
                       int kfrag8, int bk80, int n8base, int nch,
                       float* __restrict__ out, int ldo, uint32_t* smA) {
    const int tid = threadIdx.x, warp = tid >> 5, lane = tid & 31;
    const int mw = warp >> 3, nt = (warp >> 2) & 1, kd = warp & 3;
    const int gid = lane >> 2, tig = lane & 3;
    const int row = tid >> 4, q = tid & 15;          // a_pack ids
    const int tr = row & 15, mt = row >> 4;
    uint32_t* As_hi = smA;
    uint32_t* As_lo = smA + 4096;

    float c[4][4];
#pragma unroll
    for (int i = 0; i < 4; i++)
#pragma unroll
        for (int j = 0; j < 4; j++) c[i][j] = 0.f;

#pragma unroll 1
    for (int ch = 0; ch < nch; ch++) {
        __syncthreads();
        {   // pack one 64x64 A chunk into hi/lo fragments
            float4 v = __ldcg((const float4*)(X + (size_t)row * ldx + xk0 +
                                              ch * 64 + q * 4));
            float xv[4] = {v.x, v.y, v.z, v.w};
            const int k8 = q >> 1;
            const int regb = (tr >= 8 ? 1 : 0) + ((q & 1) ? 2 : 0);
#pragma unroll
            for (int j = 0; j < 4; j++) {
                int idx = ((k8 * 4 + mt) * 32 + (tr & 7) * 4 + j) * 4 + regb;
                uint32_t hb = f2tf32(xv[j]);
                As_hi[idx] = hb;
                As_lo[idx] = f2tf32(xv[j] - __uint_as_float(hb));
            }
        }
        __syncthreads();
#pragma unroll
        for (int kk = 0; kk < 2; kk++) {
            const int k8l = kd * 2 + kk;
            const int ai = ((k8l * 4 + mw) * 32 + lane) * 4;
            uint4 ah = *(const uint4*)&As_hi[ai];
            uint4 al = *(const uint4*)&As_lo[ai];
            const int k8g = bk80 + ch * 8 + k8l;
#pragma unroll
            for (int t8 = 0; t8 < 4; t8++) {
                const int n8g = n8base + nt * 4 + t8;
                const size_t ba = ((size_t)(n8g * kfrag8 + k8g) * 32 + lane) * 2;
                float2 bh = *(const float2*)&Bhi[ba];
                float2 bl = *(const float2*)&Blo[ba];
                uint32_t bh0 = __float_as_uint(bh.x), bh1 = __float_as_uint(bh.y);
                mma8(c[t8], ah, bh0, bh1);
                mma8(c[t8], ah, __float_as_uint(bl.x), __float_as_uint(bl.y));
                mma8(c[t8], al, bh0, bh1);
            }
        }
    }

    // kd-reduce via smem (reuse As buffer), then kd==0 stores
    __syncthreads();
    float* smC = (float*)smA;
    const int rid = mw * 2 + nt;
#pragma unroll
    for (int rnd = 0; rnd < 2; rnd++) {
        const int src = rnd == 0 ? 1 : 2;        // kd writing this round
        const int src2 = rnd == 0 ? 3 : -1;
        if (kd == src || kd == src2) {
            float* buf = smC + (kd == 3 ? 4096 : 0);
#pragma unroll
            for (int t8 = 0; t8 < 4; t8++) {
                int off = rid * 512 + gid * 32 + t8 * 8 + tig * 2;
                *(float2*)&buf[off]           = make_float2(c[t8][0], c[t8][1]);
                *(float2*)&buf[off + 8 * 32]  = make_float2(c[t8][2], c[t8][3]);
            }
        }
        __syncthreads();
        if ((rnd == 0 && (kd == 0 || kd == 2)) || (rnd == 1 && kd == 0)) {
            float* buf = smC + ((rnd == 0 && kd == 2) ? 4096 : 0);
#pragma unroll
            for (int t8 = 0; t8 < 4; t8++) {
                int off = rid * 512 + gid * 32 + t8 * 8 + tig * 2;
                float2 a0 = *(const float2*)&buf[off];
                float2 a1 = *(const float2*)&buf[off + 8 * 32];
                c[t8][0] += a0.x; c[t8][1] += a0.y;
                c[t8][2] += a1.x; c[t8][3] += a1.y;
            }
        }
        __syncthreads();
    }
    if (kd == 0) {
#pragma unroll
        for (int t8 = 0; t8 < 4; t8++) {
            const int n = n8base * 8 + nt * 32 + t8 * 8 + tig * 2;
            const int m = mw * 16 + gid;
            *(float2*)&out[(size_t)m * ldo + n] = make_float2(c[t8][0], c[t8][1]);
            *(float2*)&out[(size_t)(m + 8) * ldo + n] = make_float2(c[t8][2], c[t8][3]);
        }
    }
}

// ---------------- reductions (1024 threads, 32 warps) --------------------
__device__ __forceinline__ float wred(float s) {
#pragma unroll
    for (int o = 16; o > 0; o >>= 1) s += __shfl_down_sync(0xffffffffu, s, o);
    return s;
}
// stage2: warp x < nv reduces red[0..31][x]
__device__ __forceinline__ void stage2(int nv, float* bc, float (*red)[21]) {
    const int lane = threadIdx.x & 31, warp = threadIdx.x >> 5;
    __syncthreads();
    if (warp < nv) {
        float s = wred(red[lane][warp]);
        if (lane == 0) bc[warp] = s;
    }
    __syncthreads();
}

// ---------------- refine phase (block = batch element, runtime t) -------
__device__ void refine_phase(int b, int t, bool last,
                             const float* __restrict__ b_h,
                             const float* __restrict__ gam,
                             const float* __restrict__ bet,
                             const float* __restrict__ alp) {
    const int i = threadIdx.x, lane = i & 31, warp = i >> 5;

    __shared__ float red[32][21];
    __shared__ float bcS[20];
    __shared__ float bc0[20];
    __shared__ float Gs[256];
    __shared__ float hsums[16];
    __shared__ float es[16];
    __shared__ float coef[4];

    const float g0 = gam[i], be0 = bet[i];

    float hb = b_h[i] + __ldcg(&g_zwg[((size_t)t * BATCH + b) * DH + i]);
    if (t > 0) {
#pragma unroll
        for (int s = 0; s < KS_H; s++) hb += __ldcg(&g_parts[s][b * DH + i]);
    }

    float hv[15];
#pragma unroll
    for (int tau = 0; tau < 15; tau++) {
        if (tau >= t) break;
        hv[tau] = g_hist[tau][b * DH + i];
    }

    if (i < 256) Gs[i] = g_gram[b * 256 + i];
    if (i < 16)  hsums[i] = g_hsum[b * 16 + i];

    // init reduction: hb.h_tau (t), sum hb, sum hb^2  -> bc0[0..t+1]
#pragma unroll
    for (int x = 0; x < 15; x++) {
        if (x >= t) break;
        float s = wred(hv[x] * hb);
        if (lane == 0) red[warp][x] = s;
    }
    {
        float s = wred(hb);
        if (lane == 0) red[warp][t] = s;
        s = wred(hb * hb);
        if (lane == 0) red[warp][t + 1] = s;
    }
    stage2(t + 2, bc0, red);

    float mu = bc0[t] * (1.f / DH);
    float var = bc0[t + 1] * (1.f / DH) - mu * mu;
    float rstd = rsqrtf(var + 1e-5f);
    float h = fmaxf((hb - mu) * rstd * g0 + be0, 0.f);

    const float alpha = *alp;
    float wdl = 0.f;
    if (warp == 0 && lane < t)
        wdl = ETA * powf(LAMBDA, (float)(t - 1 - lane));

    for (int s = 0; s < S_STEPS; s++) {
        // one reduction: d[tau]=h.h_tau (t) + h.h
#pragma unroll
        for (int x = 0; x < 15; x++) {
            if (x >= t) break;
            float v = wred(hv[x] * h);
            if (lane == 0) red[warp][x] = v;
        }
        {
            float v = wred(h * h);
            if (lane == 0) red[warp][t] = v;
        }
        stage2(t + 1, bcS, red);

        if (warp == 0) {
            float d = (lane < t) ? bcS[lane] : 0.f;
            float e = wdl * d;
            if (lane < 16) es[lane] = e;
            __syncwarp();
            float f = 0.f;
            if (lane < t) {
                for (int sg = 0; sg < t; sg++)
                    f += es[sg] * Gs[lane * 16 + sg];
            }
            float hbd = (lane < t) ? bc0[lane] : 0.f;
            float hsm = (lane < t) ? hsums[lane] : 0.f;
            float pA = e * d, pB = e * hbd, pC = e * hsm, pD = e * f;
#pragma unroll
            for (int o = 8; o > 0; o >>= 1) {
                pA += __shfl_down_sync(0xffffffffu, pA, o);
                pB += __shfl_down_sync(0xffffffffu, pB, o);
                pC += __shfl_down_sync(0xffffffffu, pC, o);
                pD += __shfl_down_sync(0xffffffffu, pD, o);
            }
            if (lane == 0) {
                float c1, c2;
                if (!last) {
                    float hh = bcS[t];
                    float n1 = sqrtf(hh) + 1e-6f;
                    float n2 = sqrtf(fmaxf(pD, 0.f)) + 1e-6f;
                    float R  = pA / (n1 * n2 + 1e-6f);
                    float Rp = fminf(fmaxf(R, 0.f), 1.f);
                    float spp = fmaxf(alpha, 0.f) + log1pf(expf(-fabsf(alpha)));
                    float spn = fmaxf(-alpha, 0.f) + log1pf(expf(-fabsf(alpha)));
                    float kco = (alpha >= 0.f) ? (1.f + spp) : (1.f / (1.f + spn));
                    float a   = 1.f - powf(1.f - Rp, kco);
                    c1 = 1.f - a * a;
                    c2 = a;
                } else {
                    c1 = 1.f;
                    c2 = 1.f;
                }
                float sum_hn  = c1 * bc0[t] + c2 * pC;
                float sum_hn2 = c1 * c1 * bc0[t + 1] + 2.f * c1 * c2 * pB +
                                c2 * c2 * pD;
                float mu_n  = sum_hn * (1.f / DH);
                float var_n = sum_hn2 * (1.f / DH) - mu_n * mu_n;
                coef[0] = c1; coef[1] = c2;
                coef[2] = mu_n; coef[3] = rsqrtf(var_n + 1e-5f);
            }
        }
        __syncthreads();

        float Ah = 0.f;
#pragma unroll
        for (int tau = 0; tau < 15; tau++) {
            if (tau >= t) break;
            Ah += es[tau] * hv[tau];
        }
        float hn = coef[0] * hb + coef[1] * Ah;
        h = fmaxf((hn - coef[2]) * coef[3] * g0 + be0, 0.f);
        __syncthreads();
    }

    g_h[b * DH + i] = h;

    if (!last) {
        // append: Gram row/col t, sums
#pragma unroll
        for (int x = 0; x < 15; x++) {
            if (x >= t) break;
            float v = wred(hv[x] * h);
            if (lane == 0) red[warp][x] = v;
        }
        {
            float v = wred(h);
            if (lane == 0) red[warp][t] = v;
            v = wred(h * h);
            if (lane == 0) red[warp][t + 1] = v;
        }
        stage2(t + 2, bcS, red);
        if (i < t) {
            g_gram[b * 256 + t * 16 + i] = bcS[i];
            g_gram[b * 256 + i * 16 + t] = bcS[i];
        }
        if (i == 0) {
            g_gram[b * 256 + t * 16 + t] = bcS[t + 1];
            g_hsum[b * 16 + t] = bcS[t];
        }
        g_hist[t][b * DH + i] = h;
    }
}

// ---------------- loss phase ----------------
__device__ void loss_phase(int b, const float* __restrict__ clean,
                           const float* __restrict__ head_b) {
    const int o = threadIdx.x, lane = o & 31, warp = o >> 5;
    __shared__ float red[32][21];
    __shared__ float bc[20];
    float v0 = 0.f, v1 = 0.f, v2 = 0.f, v3 = 0.f;
    if (o < DOUT) {
        float pred = head_b[o];
#pragma unroll
        for (int s = 0; s < KS_O; s++) pred += __ldcg(&g_hp[s][b * DOUT + o]);
        float c = clean[b * DOUT + o];
        float d = pred - c;
        v0 = pred * c; v1 = pred * pred; v2 = c * c; v3 = d * d;
    }
    float s0 = wred(v0), s1 = wred(v1), s2 = wred(v2), s3 = wred(v3);
    if (lane == 0) {
        red[warp][0] = s0; red[warp][1] = s1;
        red[warp][2] = s2; red[warp][3] = s3;
    }
    stage2(4, bc, red);
    if (o == 0) {
        g_lossb[b] = bc[3] / (bc[2] + 1e-6f);
        g_accb[b]  = bc[0] / ((sqrtf(bc[1]) + 1e-6f) * (sqrtf(bc[2]) + 1e-6f));
    }
}

// ---------------- the one persistent kernel ----------------
__global__ void __launch_bounds__(NTHR, 1) fused_kernel(
    const float* __restrict__ z_seq, const float* __restrict__ clean,
    const float* __restrict__ W_h, const float* __restrict__ W_g,
    const float* __restrict__ b_h, const float* __restrict__ ln_g,
    const float* __restrict__ ln_b, const float* __restrict__ alpha,
    const float* __restrict__ head_W, const float* __restrict__ head_b,
    float* __restrict__ out) {
    __shared__ __align__(16) uint32_t smA[8192];   // 32 KB (A-frags / k-reduce)

    unsigned gen = g_bar_gen;
    const int bi = blockIdx.x;

    // phase 0: prepack weights
    pack_w(W_h,    g_whf_hi, g_whf_lo, DH * DH,   10, DH / 8);
    pack_w(W_g,    g_wgf_hi, g_wgf_lo, DH * DG,    9, DG / 8);
    pack_w(head_W, g_hwf_hi, g_hwf_lo, DOUT * DH, 10, DH / 8);
    bar_sync(gen);

    // phase 1: zwg = z @ W_g^T (1024x1024x512): 256 tiles, 2 per block
#pragma unroll 1
    for (int rep = 0; rep < 2; rep++) {
        const int tile = bi + rep * NBLK;
        const int mt = tile >> 4, ntile = tile & 15;
        gemm64(z_seq + (size_t)mt * 64 * DG, DG, 0,
               g_wgf_hi, g_wgf_lo, DG / 8, 0, ntile * 8, 8,
               g_zwg + (size_t)mt * 64 * DH, DH, smA);
    }
    bar_sync(gen);

    for (int t = 0; t < T_STEPS; t++) {
        if (t > 0) {
            // wh: 16 n-tiles x 8 k-splits = 128 blocks, k=128 each
            const int ntile = bi & 15, ks = bi >> 4;
            gemm64(g_h, DH, ks * 128,
                   g_whf_hi, g_whf_lo, DH / 8, ks * 16, ntile * 8, 2,
                   g_parts[ks], DH, smA);
            bar_sync(gen);
        }
        if (bi < BATCH)
            refine_phase(bi, t, t == T_STEPS - 1, b_h, ln_g, ln_b, alpha);
        bar_sync(gen);
    }

    // head: 8 n-tiles x 8 k-splits = 64 blocks, k=128 each
    if (bi < 64) {
        const int ntile = bi & 7, ks = bi >> 3;
        gemm64(g_h, DH, ks * 128,
               g_hwf_hi, g_hwf_lo, DH / 8, ks * 16, ntile * 8, 2,
               g_hp[ks], DOUT, smA);
    }
    bar_sync(gen);

    if (bi < BATCH) loss_phase(bi, clean, head_b);
    bar_sync(gen);

    if (bi == 0 && threadIdx.x < 32) {
        const int lane = threadIdx.x;
        float l = g_lossb[lane] + g_lossb[lane + 32];
        float a = g_accb[lane] + g_accb[lane + 32];
#pragma unroll
        for (int o = 16; o > 0; o >>= 1) {
            l += __shfl_down_sync(0xffffffffu, l, o);
            a += __shfl_down_sync(0xffffffffu, a, o);
        }
        if (lane == 0) {
            out[0] = l * (1.f / BATCH);
            out[1] = a * (1.f / BATCH);
        }
    }
}

// ---------------- launch ----------------
extern "C" void kernel_launch(void* const* d_in, const int* in_sizes, int n_in,
                              void* d_out, int out_size) {
    const float* z_seq  = (const float*)d_in[0];
    const float* clean  = (const float*)d_in[1];
    const float* W_h    = (const float*)d_in[2];
    const float* W_g    = (const float*)d_in[3];
    const float* b_h    = (const float*)d_in[4];
    const float* ln_g   = (const float*)d_in[5];
    const float* ln_b   = (const float*)d_in[6];
    const float* alpha  = (const float*)d_in[7];
    const float* head_W = (const float*)d_in[8];
    const float* head_b = (const float*)d_in[9];
    float* out = (float*)d_out;

    fused_kernel<<<NBLK, NTHR>>>(z_seq, clean, W_h, W_g, b_h, ln_g, ln_b,
                                 alpha, head_W, head_b, out);
}